// round 1
// baseline (speedup 1.0000x reference)
#include <cuda_runtime.h>
#include <math.h>

#define D_MODEL 1024
#define NHEAD 16
#define HD 64
#define BATCH 8
#define TQ 1024
#define TK 1024

// Scratch (static __device__ arrays; no allocation allowed)
__device__ float g_Q[BATCH * TQ * D_MODEL];
__device__ float g_K[BATCH * TK * D_MODEL];
__device__ float g_V[BATCH * TK * D_MODEL];
__device__ float g_O[BATCH * TQ * D_MODEL];
__device__ float g_L[BATCH * NHEAD * TQ];

// ---------------------------------------------------------------------------
// C[M,N] = A[M,K] @ W[N,K]^T + bias   (all row-major, M,N,K multiples of 128/16)
// BM=BN=128, BK=16, 256 threads, 8x8 micro-tile.
// ---------------------------------------------------------------------------
__global__ __launch_bounds__(256) void gemm_bias_kernel(
    const float* __restrict__ A, const float* __restrict__ W,
    const float* __restrict__ bias, float* __restrict__ C,
    int M, int N, int K)
{
    __shared__ float As[16][132];
    __shared__ float Ws[16][132];

    const int tid = threadIdx.x;
    const int bx = blockIdx.x;   // N tile
    const int by = blockIdx.y;   // M tile
    const int tx = tid & 15;     // 0..15 -> n
    const int ty = tid >> 4;     // 0..15 -> m
    const int rowL = tid >> 2;        // 0..63
    const int c4   = (tid & 3) << 2;  // 0,4,8,12

    const float* Ap = A + (size_t)(by * 128 + rowL) * K + c4;
    const float* Wp = W + (size_t)(bx * 128 + rowL) * K + c4;

    float acc[8][8];
#pragma unroll
    for (int i = 0; i < 8; ++i)
#pragma unroll
        for (int j = 0; j < 8; ++j) acc[i][j] = 0.f;

    for (int k0 = 0; k0 < K; k0 += 16) {
        float4 a0 = *(const float4*)(Ap + k0);
        float4 a1 = *(const float4*)(Ap + k0 + (size_t)64 * K);
        float4 w0 = *(const float4*)(Wp + k0);
        float4 w1 = *(const float4*)(Wp + k0 + (size_t)64 * K);
        __syncthreads();
        As[c4 + 0][rowL] = a0.x; As[c4 + 1][rowL] = a0.y;
        As[c4 + 2][rowL] = a0.z; As[c4 + 3][rowL] = a0.w;
        As[c4 + 0][rowL + 64] = a1.x; As[c4 + 1][rowL + 64] = a1.y;
        As[c4 + 2][rowL + 64] = a1.z; As[c4 + 3][rowL + 64] = a1.w;
        Ws[c4 + 0][rowL] = w0.x; Ws[c4 + 1][rowL] = w0.y;
        Ws[c4 + 2][rowL] = w0.z; Ws[c4 + 3][rowL] = w0.w;
        Ws[c4 + 0][rowL + 64] = w1.x; Ws[c4 + 1][rowL + 64] = w1.y;
        Ws[c4 + 2][rowL + 64] = w1.z; Ws[c4 + 3][rowL + 64] = w1.w;
        __syncthreads();
#pragma unroll
        for (int kk = 0; kk < 16; ++kk) {
            float ar[8], br[8];
            *(float4*)(ar)     = *(const float4*)&As[kk][ty * 8];
            *(float4*)(ar + 4) = *(const float4*)&As[kk][ty * 8 + 4];
            *(float4*)(br)     = *(const float4*)&Ws[kk][tx * 8];
            *(float4*)(br + 4) = *(const float4*)&Ws[kk][tx * 8 + 4];
#pragma unroll
            for (int i = 0; i < 8; ++i)
#pragma unroll
                for (int j = 0; j < 8; ++j)
                    acc[i][j] = fmaf(ar[i], br[j], acc[i][j]);
        }
    }

#pragma unroll
    for (int i = 0; i < 8; ++i) {
        const size_t row = (size_t)(by * 128 + ty * 8 + i);
        const int col0 = bx * 128 + tx * 8;
#pragma unroll
        for (int j = 0; j < 8; ++j) {
            C[row * N + col0 + j] = acc[i][j] + __ldg(&bias[col0 + j]);
        }
    }
}

// ---------------------------------------------------------------------------
// Attention: per (b, h, q-tile of 128). Single pass over K (no max shift:
// |scores| < ~4, exp is safe). Computes O = softmax(QK^T/8 + covbias) @ V
// and stores row sums l to g_L.
// 256 threads: ty=tid/16 -> q0=ty*8, tx=tid%16 -> x0=tx*4 (k or dv).
// ---------------------------------------------------------------------------
#define ATTN_SMEM_FLOATS (64 * 129 + 64 * 65 + 64 * 64 + 64 * 129 + 128 + 64)

__global__ __launch_bounds__(256) void attn_kernel(
    const float* __restrict__ coverage, const float* __restrict__ Wcov)
{
    extern __shared__ float sm[];
    float* Qs = sm;                  // [d=64][q=128] stride 129
    float* Ks = Qs + 64 * 129;       // [d=64][k=64]  stride 65
    float* Vs = Ks + 64 * 65;        // [k=64][dv=64] stride 64
    float* Es = Vs + 64 * 64;        // [k=64][q=128] stride 129
    float* ls = Es + 64 * 129;       // [128]
    float* cb = ls + 128;            // [64]

    const int qt = blockIdx.x;       // 0..7
    const int h  = blockIdx.y;       // 0..15
    const int b  = blockIdx.z;       // 0..7
    const int tid = threadIdx.x;
    const int tx = tid & 15, ty = tid >> 4;
    const int q0 = ty * 8;
    const int x0 = tx * 4;

    const float wch = __ldg(&Wcov[h]);

    // Load Q tile transposed: Qs[d][q]
    {
        const float* Qg = g_Q + ((size_t)(b * TQ + qt * 128)) * D_MODEL + h * HD;
        for (int i = tid; i < 128 * 16; i += 256) {
            int q = i >> 4; int d4 = (i & 15) << 2;
            float4 v = *(const float4*)(Qg + (size_t)q * D_MODEL + d4);
            Qs[(d4 + 0) * 129 + q] = v.x;
            Qs[(d4 + 1) * 129 + q] = v.y;
            Qs[(d4 + 2) * 129 + q] = v.z;
            Qs[(d4 + 3) * 129 + q] = v.w;
        }
    }
    if (tid < 128) ls[tid] = 0.f;

    float acc[8][4];
#pragma unroll
    for (int i = 0; i < 8; ++i)
#pragma unroll
        for (int j = 0; j < 4; ++j) acc[i][j] = 0.f;
    float lpart[8] = {0, 0, 0, 0, 0, 0, 0, 0};

    for (int kt = 0; kt < 16; ++kt) {
        __syncthreads();   // protect Ks/Vs/Es from previous iteration readers
        const float* Kg = g_K + ((size_t)(b * TK + kt * 64)) * D_MODEL + h * HD;
        const float* Vg = g_V + ((size_t)(b * TK + kt * 64)) * D_MODEL + h * HD;
        for (int i = tid; i < 64 * 16; i += 256) {
            int k = i >> 4; int d4 = (i & 15) << 2;
            float4 kv = *(const float4*)(Kg + (size_t)k * D_MODEL + d4);
            Ks[(d4 + 0) * 65 + k] = kv.x;
            Ks[(d4 + 1) * 65 + k] = kv.y;
            Ks[(d4 + 2) * 65 + k] = kv.z;
            Ks[(d4 + 3) * 65 + k] = kv.w;
            float4 vv = *(const float4*)(Vg + (size_t)k * D_MODEL + d4);
            *(float4*)(Vs + k * 64 + d4) = vv;
        }
        if (tid < 64) cb[tid] = __ldg(&coverage[b * TK + kt * 64 + tid]) * wch;
        __syncthreads();

        // S = Q K^T (micro 8q x 4k)
        float s[8][4];
#pragma unroll
        for (int i = 0; i < 8; ++i)
#pragma unroll
            for (int j = 0; j < 4; ++j) s[i][j] = 0.f;
#pragma unroll 8
        for (int d = 0; d < 64; ++d) {
            float a[8], bb[4];
#pragma unroll
            for (int i = 0; i < 8; ++i) a[i] = Qs[d * 129 + q0 + i];
#pragma unroll
            for (int j = 0; j < 4; ++j) bb[j] = Ks[d * 65 + x0 + j];
#pragma unroll
            for (int i = 0; i < 8; ++i)
#pragma unroll
                for (int j = 0; j < 4; ++j)
                    s[i][j] = fmaf(a[i], bb[j], s[i][j]);
        }
        // e = exp(s/8 + covbias), store transposed Es[k][q], accumulate l
#pragma unroll
        for (int j = 0; j < 4; ++j) {
            const float cbv = cb[x0 + j];
#pragma unroll
            for (int i = 0; i < 8; ++i) {
                float e = __expf(fmaf(s[i][j], 0.125f, cbv));
                Es[(x0 + j) * 129 + q0 + i] = e;
                lpart[i] += e;
            }
        }
        __syncthreads();

        // O += E^T-form: O[q][dv] += sum_k Es[k][q] * Vs[k][dv]
#pragma unroll 8
        for (int k = 0; k < 64; ++k) {
            float a[8];
#pragma unroll
            for (int i = 0; i < 8; ++i) a[i] = Es[k * 129 + q0 + i];
            const float4 v4 = *(const float4*)(Vs + k * 64 + x0);
#pragma unroll
            for (int i = 0; i < 8; ++i) {
                acc[i][0] = fmaf(a[i], v4.x, acc[i][0]);
                acc[i][1] = fmaf(a[i], v4.y, acc[i][1]);
                acc[i][2] = fmaf(a[i], v4.z, acc[i][2]);
                acc[i][3] = fmaf(a[i], v4.w, acc[i][3]);
            }
        }
    }

#pragma unroll
    for (int i = 0; i < 8; ++i) atomicAdd(&ls[q0 + i], lpart[i]);
    __syncthreads();

    // normalize + write O, store l
    float* Og = g_O + ((size_t)(b * TQ + qt * 128)) * D_MODEL + h * HD;
#pragma unroll
    for (int i = 0; i < 8; ++i) {
        const float inv = 1.f / ls[q0 + i];
        float4 o;
        o.x = acc[i][0] * inv; o.y = acc[i][1] * inv;
        o.z = acc[i][2] * inv; o.w = acc[i][3] * inv;
        *(float4*)(Og + (size_t)(q0 + i) * D_MODEL + x0) = o;
    }
    if (tid < 128)
        g_L[((size_t)b * NHEAD + h) * TQ + qt * 128 + tid] = ls[tid];
}

// ---------------------------------------------------------------------------
// Coverage accumulation: recompute scores, accumulate
// covout[b,k] += sum_q exp(s)/(16*l_q). Same tiling as attn_kernel.
// ---------------------------------------------------------------------------
#define COV_SMEM_FLOATS (64 * 129 + 64 * 65 + 64 * 129 + 128 + 64)

__global__ __launch_bounds__(256) void cov_kernel(
    const float* __restrict__ coverage, const float* __restrict__ Wcov,
    float* __restrict__ covout)
{
    extern __shared__ float sm[];
    float* Qs = sm;                  // [64][129]
    float* Ks = Qs + 64 * 129;       // [64][65]
    float* Es = Ks + 64 * 65;        // [64][129]
    float* il = Es + 64 * 129;       // [128]
    float* cb = il + 128;            // [64]

    const int qt = blockIdx.x;
    const int h  = blockIdx.y;
    const int b  = blockIdx.z;
    const int tid = threadIdx.x;
    const int tx = tid & 15, ty = tid >> 4;
    const int q0 = ty * 8;
    const int x0 = tx * 4;

    const float wch = __ldg(&Wcov[h]);

    {
        const float* Qg = g_Q + ((size_t)(b * TQ + qt * 128)) * D_MODEL + h * HD;
        for (int i = tid; i < 128 * 16; i += 256) {
            int q = i >> 4; int d4 = (i & 15) << 2;
            float4 v = *(const float4*)(Qg + (size_t)q * D_MODEL + d4);
            Qs[(d4 + 0) * 129 + q] = v.x;
            Qs[(d4 + 1) * 129 + q] = v.y;
            Qs[(d4 + 2) * 129 + q] = v.z;
            Qs[(d4 + 3) * 129 + q] = v.w;
        }
    }
    if (tid < 128)
        il[tid] = 1.f / (16.f * g_L[((size_t)b * NHEAD + h) * TQ + qt * 128 + tid]);

    for (int kt = 0; kt < 16; ++kt) {
        __syncthreads();
        const float* Kg = g_K + ((size_t)(b * TK + kt * 64)) * D_MODEL + h * HD;
        for (int i = tid; i < 64 * 16; i += 256) {
            int k = i >> 4; int d4 = (i & 15) << 2;
            float4 kv = *(const float4*)(Kg + (size_t)k * D_MODEL + d4);
            Ks[(d4 + 0) * 65 + k] = kv.x;
            Ks[(d4 + 1) * 65 + k] = kv.y;
            Ks[(d4 + 2) * 65 + k] = kv.z;
            Ks[(d4 + 3) * 65 + k] = kv.w;
        }
        if (tid < 64) cb[tid] = __ldg(&coverage[b * TK + kt * 64 + tid]) * wch;
        __syncthreads();

        float s[8][4];
#pragma unroll
        for (int i = 0; i < 8; ++i)
#pragma unroll
            for (int j = 0; j < 4; ++j) s[i][j] = 0.f;
#pragma unroll 8
        for (int d = 0; d < 64; ++d) {
            float a[8], bb[4];
#pragma unroll
            for (int i = 0; i < 8; ++i) a[i] = Qs[d * 129 + q0 + i];
#pragma unroll
            for (int j = 0; j < 4; ++j) bb[j] = Ks[d * 65 + x0 + j];
#pragma unroll
            for (int i = 0; i < 8; ++i)
#pragma unroll
                for (int j = 0; j < 4; ++j)
                    s[i][j] = fmaf(a[i], bb[j], s[i][j]);
        }
#pragma unroll
        for (int j = 0; j < 4; ++j) {
            const float cbv = cb[x0 + j];
#pragma unroll
            for (int i = 0; i < 8; ++i) {
                float e = __expf(fmaf(s[i][j], 0.125f, cbv)) * il[q0 + i];
                Es[(x0 + j) * 129 + q0 + i] = e;
            }
        }
        __syncthreads();
        if (tid < 64) {
            float sum = 0.f;
            const float* row = Es + tid * 129;
#pragma unroll 16
            for (int q = 0; q < 128; ++q) sum += row[q];
            atomicAdd(covout + b * TK + kt * 64 + tid, sum);
        }
    }
}

__global__ void cov_init_kernel(const float* __restrict__ coverage,
                                float* __restrict__ covout)
{
    int i = blockIdx.x * blockDim.x + threadIdx.x;
    if (i < BATCH * TK) covout[i] = coverage[i];
}

// ---------------------------------------------------------------------------
extern "C" void kernel_launch(void* const* d_in, const int* in_sizes, int n_in,
                              void* d_out, int out_size)
{
    const float* query    = (const float*)d_in[0];
    const float* memory   = (const float*)d_in[1];
    const float* coverage = (const float*)d_in[2];
    const float* Wq = (const float*)d_in[3];
    const float* bq = (const float*)d_in[4];
    const float* Wk = (const float*)d_in[5];
    const float* bk = (const float*)d_in[6];
    const float* Wv = (const float*)d_in[7];
    const float* bv = (const float*)d_in[8];
    const float* Wo = (const float*)d_in[9];
    const float* bo = (const float*)d_in[10];
    const float* Wcov = (const float*)d_in[11];

    float* out = (float*)d_out;
    float* covout = out + (size_t)BATCH * TQ * D_MODEL;

    float *Qp, *Kp, *Vp, *Op;
    cudaGetSymbolAddress((void**)&Qp, g_Q);
    cudaGetSymbolAddress((void**)&Kp, g_K);
    cudaGetSymbolAddress((void**)&Vp, g_V);
    cudaGetSymbolAddress((void**)&Op, g_O);

    const int M = BATCH * TQ;   // 8192
    const dim3 ggrid(D_MODEL / 128, M / 128);

    static int configured = 0;
    // (setting attributes is idempotent and not stream-ordered; safe in capture)
    cudaFuncSetAttribute(attn_kernel, cudaFuncAttributeMaxDynamicSharedMemorySize,
                         ATTN_SMEM_FLOATS * 4);
    cudaFuncSetAttribute(cov_kernel, cudaFuncAttributeMaxDynamicSharedMemorySize,
                         COV_SMEM_FLOATS * 4);
    (void)configured;

    gemm_bias_kernel<<<ggrid, 256>>>(query,  Wq, bq, Qp, M, D_MODEL, D_MODEL);
    gemm_bias_kernel<<<ggrid, 256>>>(memory, Wk, bk, Kp, M, D_MODEL, D_MODEL);
    gemm_bias_kernel<<<ggrid, 256>>>(memory, Wv, bv, Vp, M, D_MODEL, D_MODEL);

    attn_kernel<<<dim3(TQ / 128, NHEAD, BATCH), 256, ATTN_SMEM_FLOATS * 4>>>(coverage, Wcov);

    gemm_bias_kernel<<<ggrid, 256>>>(Op, Wo, bo, out, M, D_MODEL, D_MODEL);

    cov_init_kernel<<<(BATCH * TK + 255) / 256, 256>>>(coverage, covout);
    cov_kernel<<<dim3(TQ / 128, NHEAD, BATCH), 256, COV_SMEM_FLOATS * 4>>>(coverage, Wcov, covout);
}

// round 5
// speedup vs baseline: 1.5516x; 1.5516x over previous
#include <cuda_runtime.h>
#include <math.h>
#include <stdint.h>

#define D_MODEL 1024
#define NHEAD 16
#define HD 64
#define BATCH 8
#define TQ 1024
#define TK 1024

// Scratch (static __device__ arrays; no allocation allowed)
__device__ float g_Q[BATCH * TQ * D_MODEL];
__device__ float g_K[BATCH * TK * D_MODEL];
__device__ float g_V[BATCH * TK * D_MODEL];
__device__ float g_O[BATCH * TQ * D_MODEL];
__device__ float g_L[BATCH * NHEAD * TQ];

__device__ __forceinline__ uint32_t cvt_tf32(float f) {
    uint32_t o;
    asm("cvt.rna.tf32.f32 %0, %1;" : "=r"(o) : "f"(f));
    return o;
}

// ---------------------------------------------------------------------------
// mma.sync tf32 GEMM:  C[M,N] = A[M,K] @ W[N,K]^T + bias  (row-major)
// CTA tile 128x128, BK=32, 256 threads (8 warps), warp tile 64x32,
// m16n8k8 tf32 fragments, double-buffered smem.
// ---------------------------------------------------------------------------
#define GEMM_SMEM_U32 (4 * 128 * 36)            // 2 stages x (A + W) x 128x36
#define GEMM_DSMEM (GEMM_SMEM_U32 * 4)          // 73728 bytes

__global__ __launch_bounds__(256) void gemm_mma_kernel(
    const float* __restrict__ A, const float* __restrict__ W,
    const float* __restrict__ bias, float* __restrict__ C,
    int M, int N, int K)
{
    extern __shared__ uint32_t smu[];
    uint32_t* AsB = smu;                    // [2][128*36]
    uint32_t* WsB = smu + 2 * 128 * 36;     // [2][128*36]

    const int t = threadIdx.x;
    const int lane = t & 31, w = t >> 5;
    const int bx = blockIdx.x;   // N tile
    const int by = blockIdx.y;   // M tile
    const int wm = (w & 1) * 64;     // warp row offset in CTA tile
    const int wn = (w >> 1) * 32;    // warp col offset
    const int g = lane >> 2, tg = lane & 3;

    const float* Ag = A + (size_t)(by * 128) * K;
    const float* Wg = W + (size_t)(bx * 128) * K;

    const int r_ld = t >> 3;          // not used directly; per-i below
    (void)r_ld;

    float acc[4][4][4];
#pragma unroll
    for (int mt = 0; mt < 4; ++mt)
#pragma unroll
        for (int nt = 0; nt < 4; ++nt)
#pragma unroll
            for (int r = 0; r < 4; ++r) acc[mt][nt][r] = 0.f;

    float4 ra[4], rw[4];

    const int NIT = K / 32;

    // prologue: load + store stage 0
#pragma unroll
    for (int i = 0; i < 4; ++i) {
        const int idx = t + 256 * i;
        const int r = idx >> 3, fq = idx & 7;
        ra[i] = *(const float4*)(Ag + (size_t)r * K + fq * 4);
        rw[i] = *(const float4*)(Wg + (size_t)r * K + fq * 4);
    }
#pragma unroll
    for (int i = 0; i < 4; ++i) {
        const int idx = t + 256 * i;
        const int r = idx >> 3, fq = idx & 7;
        uint4 pa, pb;
        pa.x = cvt_tf32(ra[i].x); pa.y = cvt_tf32(ra[i].y);
        pa.z = cvt_tf32(ra[i].z); pa.w = cvt_tf32(ra[i].w);
        pb.x = cvt_tf32(rw[i].x); pb.y = cvt_tf32(rw[i].y);
        pb.z = cvt_tf32(rw[i].z); pb.w = cvt_tf32(rw[i].w);
        *(uint4*)&AsB[r * 36 + fq * 4] = pa;
        *(uint4*)&WsB[r * 36 + fq * 4] = pb;
    }
    __syncthreads();

    for (int it = 0; it < NIT; ++it) {
        const int s = it & 1;
        if (it + 1 < NIT) {
            const int k0 = (it + 1) * 32;
#pragma unroll
            for (int i = 0; i < 4; ++i) {
                const int idx = t + 256 * i;
                const int r = idx >> 3, fq = idx & 7;
                ra[i] = *(const float4*)(Ag + (size_t)r * K + k0 + fq * 4);
                rw[i] = *(const float4*)(Wg + (size_t)r * K + k0 + fq * 4);
            }
        }

        // compute from stage s
        {
            const uint32_t* as = AsB + s * (128 * 36);
            const uint32_t* ws = WsB + s * (128 * 36);
#pragma unroll
            for (int kk = 0; kk < 4; ++kk) {
                const int k0 = kk * 8;
                uint32_t af[4][4];
#pragma unroll
                for (int mt = 0; mt < 4; ++mt) {
                    const int r0 = wm + mt * 16 + g;
                    af[mt][0] = as[r0 * 36 + k0 + tg];
                    af[mt][1] = as[(r0 + 8) * 36 + k0 + tg];
                    af[mt][2] = as[r0 * 36 + k0 + 4 + tg];
                    af[mt][3] = as[(r0 + 8) * 36 + k0 + 4 + tg];
                }
#pragma unroll
                for (int nt = 0; nt < 4; ++nt) {
                    const int c0 = wn + nt * 8 + g;
                    const uint32_t b0 = ws[c0 * 36 + k0 + tg];
                    const uint32_t b1 = ws[c0 * 36 + k0 + 4 + tg];
#pragma unroll
                    for (int mt = 0; mt < 4; ++mt) {
                        asm volatile(
                            "mma.sync.aligned.m16n8k8.row.col.f32.tf32.tf32.f32 "
                            "{%0,%1,%2,%3}, {%4,%5,%6,%7}, {%8,%9}, {%0,%1,%2,%3};"
                            : "+f"(acc[mt][nt][0]), "+f"(acc[mt][nt][1]),
                              "+f"(acc[mt][nt][2]), "+f"(acc[mt][nt][3])
                            : "r"(af[mt][0]), "r"(af[mt][1]),
                              "r"(af[mt][2]), "r"(af[mt][3]),
                              "r"(b0), "r"(b1));
                    }
                }
            }
        }

        if (it + 1 < NIT) {
            uint32_t* as = AsB + (s ^ 1) * (128 * 36);
            uint32_t* ws = WsB + (s ^ 1) * (128 * 36);
#pragma unroll
            for (int i = 0; i < 4; ++i) {
                const int idx = t + 256 * i;
                const int r = idx >> 3, fq = idx & 7;
                uint4 pa, pb;
                pa.x = cvt_tf32(ra[i].x); pa.y = cvt_tf32(ra[i].y);
                pa.z = cvt_tf32(ra[i].z); pa.w = cvt_tf32(ra[i].w);
                pb.x = cvt_tf32(rw[i].x); pb.y = cvt_tf32(rw[i].y);
                pb.z = cvt_tf32(rw[i].z); pb.w = cvt_tf32(rw[i].w);
                *(uint4*)&as[r * 36 + fq * 4] = pa;
                *(uint4*)&ws[r * 36 + fq * 4] = pb;
            }
        }
        __syncthreads();
    }

    // epilogue + bias
#pragma unroll
    for (int mt = 0; mt < 4; ++mt) {
        const int row0 = by * 128 + wm + mt * 16 + g;
#pragma unroll
        for (int nt = 0; nt < 4; ++nt) {
            const int col = bx * 128 + wn + nt * 8 + 2 * tg;
            const float2 b01 = *(const float2*)(bias + col);
            float2 v0, v1;
            v0.x = acc[mt][nt][0] + b01.x;
            v0.y = acc[mt][nt][1] + b01.y;
            v1.x = acc[mt][nt][2] + b01.x;
            v1.y = acc[mt][nt][3] + b01.y;
            *(float2*)(C + (size_t)row0 * N + col) = v0;
            *(float2*)(C + (size_t)(row0 + 8) * N + col) = v1;
        }
    }
}

// ---------------------------------------------------------------------------
// Attention: per (b, h, q-tile of 128). Single pass over K (no max shift:
// |scores| < ~4, exp is safe). Computes O = softmax(QK^T/8 + covbias) @ V
// and stores row sums l to g_L.
// ---------------------------------------------------------------------------
#define ATTN_SMEM_FLOATS (64 * 129 + 64 * 65 + 64 * 64 + 64 * 129 + 128 + 64)

__global__ __launch_bounds__(256) void attn_kernel(
    const float* __restrict__ coverage, const float* __restrict__ Wcov)
{
    extern __shared__ float sm[];
    float* Qs = sm;                  // [d=64][q=128] stride 129
    float* Ks = Qs + 64 * 129;       // [d=64][k=64]  stride 65
    float* Vs = Ks + 64 * 65;        // [k=64][dv=64] stride 64
    float* Es = Vs + 64 * 64;        // [k=64][q=128] stride 129
    float* ls = Es + 64 * 129;       // [128]
    float* cb = ls + 128;            // [64]

    const int qt = blockIdx.x;
    const int h  = blockIdx.y;
    const int b  = blockIdx.z;
    const int tid = threadIdx.x;
    const int tx = tid & 15, ty = tid >> 4;
    const int q0 = ty * 8;
    const int x0 = tx * 4;

    const float wch = __ldg(&Wcov[h]);

    {
        const float* Qg = g_Q + ((size_t)(b * TQ + qt * 128)) * D_MODEL + h * HD;
        for (int i = tid; i < 128 * 16; i += 256) {
            int q = i >> 4; int d4 = (i & 15) << 2;
            float4 v = *(const float4*)(Qg + (size_t)q * D_MODEL + d4);
            Qs[(d4 + 0) * 129 + q] = v.x;
            Qs[(d4 + 1) * 129 + q] = v.y;
            Qs[(d4 + 2) * 129 + q] = v.z;
            Qs[(d4 + 3) * 129 + q] = v.w;
        }
    }
    if (tid < 128) ls[tid] = 0.f;

    float acc[8][4];
#pragma unroll
    for (int i = 0; i < 8; ++i)
#pragma unroll
        for (int j = 0; j < 4; ++j) acc[i][j] = 0.f;
    float lpart[8] = {0, 0, 0, 0, 0, 0, 0, 0};

    for (int kt = 0; kt < 16; ++kt) {
        __syncthreads();
        const float* Kg = g_K + ((size_t)(b * TK + kt * 64)) * D_MODEL + h * HD;
        const float* Vg = g_V + ((size_t)(b * TK + kt * 64)) * D_MODEL + h * HD;
        for (int i = tid; i < 64 * 16; i += 256) {
            int k = i >> 4; int d4 = (i & 15) << 2;
            float4 kv = *(const float4*)(Kg + (size_t)k * D_MODEL + d4);
            Ks[(d4 + 0) * 65 + k] = kv.x;
            Ks[(d4 + 1) * 65 + k] = kv.y;
            Ks[(d4 + 2) * 65 + k] = kv.z;
            Ks[(d4 + 3) * 65 + k] = kv.w;
            float4 vv = *(const float4*)(Vg + (size_t)k * D_MODEL + d4);
            *(float4*)(Vs + k * 64 + d4) = vv;
        }
        if (tid < 64) cb[tid] = __ldg(&coverage[b * TK + kt * 64 + tid]) * wch;
        __syncthreads();

        float s[8][4];
#pragma unroll
        for (int i = 0; i < 8; ++i)
#pragma unroll
            for (int j = 0; j < 4; ++j) s[i][j] = 0.f;
#pragma unroll 8
        for (int d = 0; d < 64; ++d) {
            float a[8], bb[4];
#pragma unroll
            for (int i = 0; i < 8; ++i) a[i] = Qs[d * 129 + q0 + i];
#pragma unroll
            for (int j = 0; j < 4; ++j) bb[j] = Ks[d * 65 + x0 + j];
#pragma unroll
            for (int i = 0; i < 8; ++i)
#pragma unroll
                for (int j = 0; j < 4; ++j)
                    s[i][j] = fmaf(a[i], bb[j], s[i][j]);
        }
#pragma unroll
        for (int j = 0; j < 4; ++j) {
            const float cbv = cb[x0 + j];
#pragma unroll
            for (int i = 0; i < 8; ++i) {
                float e = __expf(fmaf(s[i][j], 0.125f, cbv));
                Es[(x0 + j) * 129 + q0 + i] = e;
                lpart[i] += e;
            }
        }
        __syncthreads();

#pragma unroll 8
        for (int k = 0; k < 64; ++k) {
            float a[8];
#pragma unroll
            for (int i = 0; i < 8; ++i) a[i] = Es[k * 129 + q0 + i];
            const float4 v4 = *(const float4*)(Vs + k * 64 + x0);
#pragma unroll
            for (int i = 0; i < 8; ++i) {
                acc[i][0] = fmaf(a[i], v4.x, acc[i][0]);
                acc[i][1] = fmaf(a[i], v4.y, acc[i][1]);
                acc[i][2] = fmaf(a[i], v4.z, acc[i][2]);
                acc[i][3] = fmaf(a[i], v4.w, acc[i][3]);
            }
        }
    }

#pragma unroll
    for (int i = 0; i < 8; ++i) atomicAdd(&ls[q0 + i], lpart[i]);
    __syncthreads();

    float* Og = g_O + ((size_t)(b * TQ + qt * 128)) * D_MODEL + h * HD;
#pragma unroll
    for (int i = 0; i < 8; ++i) {
        const float inv = 1.f / ls[q0 + i];
        float4 o;
        o.x = acc[i][0] * inv; o.y = acc[i][1] * inv;
        o.z = acc[i][2] * inv; o.w = acc[i][3] * inv;
        *(float4*)(Og + (size_t)(q0 + i) * D_MODEL + x0) = o;
    }
    if (tid < 128)
        g_L[((size_t)b * NHEAD + h) * TQ + qt * 128 + tid] = ls[tid];
}

// ---------------------------------------------------------------------------
// Coverage accumulation: recompute scores, accumulate
// covout[b,k] += sum_q exp(s)/(16*l_q).
// ---------------------------------------------------------------------------
#define COV_SMEM_FLOATS (64 * 129 + 64 * 65 + 64 * 129 + 128 + 64)

__global__ __launch_bounds__(256) void cov_kernel(
    const float* __restrict__ coverage, const float* __restrict__ Wcov,
    float* __restrict__ covout)
{
    extern __shared__ float sm[];
    float* Qs = sm;                  // [64][129]
    float* Ks = Qs + 64 * 129;       // [64][65]
    float* Es = Ks + 64 * 65;        // [64][129]
    float* il = Es + 64 * 129;       // [128]
    float* cb = il + 128;            // [64]

    const int qt = blockIdx.x;
    const int h  = blockIdx.y;
    const int b  = blockIdx.z;
    const int tid = threadIdx.x;
    const int tx = tid & 15, ty = tid >> 4;
    const int q0 = ty * 8;
    const int x0 = tx * 4;

    const float wch = __ldg(&Wcov[h]);

    {
        const float* Qg = g_Q + ((size_t)(b * TQ + qt * 128)) * D_MODEL + h * HD;
        for (int i = tid; i < 128 * 16; i += 256) {
            int q = i >> 4; int d4 = (i & 15) << 2;
            float4 v = *(const float4*)(Qg + (size_t)q * D_MODEL + d4);
            Qs[(d4 + 0) * 129 + q] = v.x;
            Qs[(d4 + 1) * 129 + q] = v.y;
            Qs[(d4 + 2) * 129 + q] = v.z;
            Qs[(d4 + 3) * 129 + q] = v.w;
        }
    }
    if (tid < 128)
        il[tid] = 1.f / (16.f * g_L[((size_t)b * NHEAD + h) * TQ + qt * 128 + tid]);

    for (int kt = 0; kt < 16; ++kt) {
        __syncthreads();
        const float* Kg = g_K + ((size_t)(b * TK + kt * 64)) * D_MODEL + h * HD;
        for (int i = tid; i < 64 * 16; i += 256) {
            int k = i >> 4; int d4 = (i & 15) << 2;
            float4 kv = *(const float4*)(Kg + (size_t)k * D_MODEL + d4);
            Ks[(d4 + 0) * 65 + k] = kv.x;
            Ks[(d4 + 1) * 65 + k] = kv.y;
            Ks[(d4 + 2) * 65 + k] = kv.z;
            Ks[(d4 + 3) * 65 + k] = kv.w;
        }
        if (tid < 64) cb[tid] = __ldg(&coverage[b * TK + kt * 64 + tid]) * wch;
        __syncthreads();

        float s[8][4];
#pragma unroll
        for (int i = 0; i < 8; ++i)
#pragma unroll
            for (int j = 0; j < 4; ++j) s[i][j] = 0.f;
#pragma unroll 8
        for (int d = 0; d < 64; ++d) {
            float a[8], bb[4];
#pragma unroll
            for (int i = 0; i < 8; ++i) a[i] = Qs[d * 129 + q0 + i];
#pragma unroll
            for (int j = 0; j < 4; ++j) bb[j] = Ks[d * 65 + x0 + j];
#pragma unroll
            for (int i = 0; i < 8; ++i)
#pragma unroll
                for (int j = 0; j < 4; ++j)
                    s[i][j] = fmaf(a[i], bb[j], s[i][j]);
        }
#pragma unroll
        for (int j = 0; j < 4; ++j) {
            const float cbv = cb[x0 + j];
#pragma unroll
            for (int i = 0; i < 8; ++i) {
                float e = __expf(fmaf(s[i][j], 0.125f, cbv)) * il[q0 + i];
                Es[(x0 + j) * 129 + q0 + i] = e;
            }
        }
        __syncthreads();
        if (tid < 64) {
            float sum = 0.f;
            const float* row = Es + tid * 129;
#pragma unroll 16
            for (int q = 0; q < 128; ++q) sum += row[q];
            atomicAdd(covout + b * TK + kt * 64 + tid, sum);
        }
    }
}

__global__ void cov_init_kernel(const float* __restrict__ coverage,
                                float* __restrict__ covout)
{
    int i = blockIdx.x * blockDim.x + threadIdx.x;
    if (i < BATCH * TK) covout[i] = coverage[i];
}

// ---------------------------------------------------------------------------
extern "C" void kernel_launch(void* const* d_in, const int* in_sizes, int n_in,
                              void* d_out, int out_size)
{
    const float* query    = (const float*)d_in[0];
    const float* memory   = (const float*)d_in[1];
    const float* coverage = (const float*)d_in[2];
    const float* Wq = (const float*)d_in[3];
    const float* bq = (const float*)d_in[4];
    const float* Wk = (const float*)d_in[5];
    const float* bk = (const float*)d_in[6];
    const float* Wv = (const float*)d_in[7];
    const float* bv = (const float*)d_in[8];
    const float* Wo = (const float*)d_in[9];
    const float* bo = (const float*)d_in[10];
    const float* Wcov = (const float*)d_in[11];

    float* out = (float*)d_out;
    float* covout = out + (size_t)BATCH * TQ * D_MODEL;

    float *Qp, *Kp, *Vp, *Op;
    cudaGetSymbolAddress((void**)&Qp, g_Q);
    cudaGetSymbolAddress((void**)&Kp, g_K);
    cudaGetSymbolAddress((void**)&Vp, g_V);
    cudaGetSymbolAddress((void**)&Op, g_O);

    const int M = BATCH * TQ;   // 8192
    const dim3 ggrid(D_MODEL / 128, M / 128);

    cudaFuncSetAttribute(gemm_mma_kernel, cudaFuncAttributeMaxDynamicSharedMemorySize,
                         GEMM_DSMEM);
    cudaFuncSetAttribute(attn_kernel, cudaFuncAttributeMaxDynamicSharedMemorySize,
                         ATTN_SMEM_FLOATS * 4);
    cudaFuncSetAttribute(cov_kernel, cudaFuncAttributeMaxDynamicSharedMemorySize,
                         COV_SMEM_FLOATS * 4);

    gemm_mma_kernel<<<ggrid, 256, GEMM_DSMEM>>>(query,  Wq, bq, Qp, M, D_MODEL, D_MODEL);
    gemm_mma_kernel<<<ggrid, 256, GEMM_DSMEM>>>(memory, Wk, bk, Kp, M, D_MODEL, D_MODEL);
    gemm_mma_kernel<<<ggrid, 256, GEMM_DSMEM>>>(memory, Wv, bv, Vp, M, D_MODEL, D_MODEL);

    attn_kernel<<<dim3(TQ / 128, NHEAD, BATCH), 256, ATTN_SMEM_FLOATS * 4>>>(coverage, Wcov);

    gemm_mma_kernel<<<ggrid, 256, GEMM_DSMEM>>>(Op, Wo, bo, out, M, D_MODEL, D_MODEL);

    cov_init_kernel<<<(BATCH * TK + 255) / 256, 256>>>(coverage, covout);
    cov_kernel<<<dim3(TQ / 128, NHEAD, BATCH), 256, COV_SMEM_FLOATS * 4>>>(coverage, Wcov, covout);
}

// round 6
// speedup vs baseline: 2.9263x; 1.8859x over previous
#include <cuda_runtime.h>
#include <cuda_bf16.h>
#include <math.h>
#include <stdint.h>

#define D_MODEL 1024
#define NHEAD 16
#define HD 64
#define BATCH 8
#define TQ 1024
#define TK 1024

// Scratch (static __device__ arrays; no allocation allowed)
__device__ float g_Q[BATCH * TQ * D_MODEL];
__device__ float g_K[BATCH * TK * D_MODEL];
__device__ float g_V[BATCH * TK * D_MODEL];
__device__ float g_O[BATCH * TQ * D_MODEL];
__device__ float g_L[BATCH * NHEAD * TQ];
__device__ __nv_bfloat16 g_E[BATCH * NHEAD * TQ * TK];   // unnormalized exp(scores)

__device__ __forceinline__ uint32_t cvt_tf32(float f) {
    uint32_t o;
    asm("cvt.rna.tf32.f32 %0, %1;" : "=r"(o) : "f"(f));
    return o;
}
__device__ __forceinline__ float tf32f(float f) {
    return __uint_as_float(cvt_tf32(f));
}

#define MMA_TF32(acc, a0, a1, a2, a3, b0, b1)                                   \
    asm volatile(                                                               \
        "mma.sync.aligned.m16n8k8.row.col.f32.tf32.tf32.f32 "                   \
        "{%0,%1,%2,%3}, {%4,%5,%6,%7}, {%8,%9}, {%0,%1,%2,%3};"                 \
        : "+f"((acc)[0]), "+f"((acc)[1]), "+f"((acc)[2]), "+f"((acc)[3])        \
        : "r"(a0), "r"(a1), "r"(a2), "r"(a3), "r"(b0), "r"(b1))

// ---------------------------------------------------------------------------
// mma.sync tf32 GEMM:  C[M,N] = A[M,K] @ W[N,K]^T + bias  (row-major)
// CTA tile 128x128, BK=32, 256 threads (8 warps), warp tile 64x32.
// ---------------------------------------------------------------------------
#define GEMM_SMEM_U32 (4 * 128 * 36)
#define GEMM_DSMEM (GEMM_SMEM_U32 * 4)

__global__ __launch_bounds__(256) void gemm_mma_kernel(
    const float* __restrict__ A, const float* __restrict__ W,
    const float* __restrict__ bias, float* __restrict__ C,
    int M, int N, int K)
{
    extern __shared__ uint32_t smu[];
    uint32_t* AsB = smu;
    uint32_t* WsB = smu + 2 * 128 * 36;

    const int t = threadIdx.x;
    const int lane = t & 31, w = t >> 5;
    const int bx = blockIdx.x;
    const int by = blockIdx.y;
    const int wm = (w & 1) * 64;
    const int wn = (w >> 1) * 32;
    const int g = lane >> 2, tg = lane & 3;

    const float* Ag = A + (size_t)(by * 128) * K;
    const float* Wg = W + (size_t)(bx * 128) * K;

    float acc[4][4][4];
#pragma unroll
    for (int mt = 0; mt < 4; ++mt)
#pragma unroll
        for (int nt = 0; nt < 4; ++nt)
#pragma unroll
            for (int r = 0; r < 4; ++r) acc[mt][nt][r] = 0.f;

    float4 ra[4], rw[4];
    const int NIT = K / 32;

#pragma unroll
    for (int i = 0; i < 4; ++i) {
        const int idx = t + 256 * i;
        const int r = idx >> 3, fq = idx & 7;
        ra[i] = *(const float4*)(Ag + (size_t)r * K + fq * 4);
        rw[i] = *(const float4*)(Wg + (size_t)r * K + fq * 4);
    }
#pragma unroll
    for (int i = 0; i < 4; ++i) {
        const int idx = t + 256 * i;
        const int r = idx >> 3, fq = idx & 7;
        uint4 pa, pb;
        pa.x = cvt_tf32(ra[i].x); pa.y = cvt_tf32(ra[i].y);
        pa.z = cvt_tf32(ra[i].z); pa.w = cvt_tf32(ra[i].w);
        pb.x = cvt_tf32(rw[i].x); pb.y = cvt_tf32(rw[i].y);
        pb.z = cvt_tf32(rw[i].z); pb.w = cvt_tf32(rw[i].w);
        *(uint4*)&AsB[r * 36 + fq * 4] = pa;
        *(uint4*)&WsB[r * 36 + fq * 4] = pb;
    }
    __syncthreads();

    for (int it = 0; it < NIT; ++it) {
        const int s = it & 1;
        if (it + 1 < NIT) {
            const int k0 = (it + 1) * 32;
#pragma unroll
            for (int i = 0; i < 4; ++i) {
                const int idx = t + 256 * i;
                const int r = idx >> 3, fq = idx & 7;
                ra[i] = *(const float4*)(Ag + (size_t)r * K + k0 + fq * 4);
                rw[i] = *(const float4*)(Wg + (size_t)r * K + k0 + fq * 4);
            }
        }
        {
            const uint32_t* as = AsB + s * (128 * 36);
            const uint32_t* ws = WsB + s * (128 * 36);
#pragma unroll
            for (int kk = 0; kk < 4; ++kk) {
                const int k0 = kk * 8;
                uint32_t af[4][4];
#pragma unroll
                for (int mt = 0; mt < 4; ++mt) {
                    const int r0 = wm + mt * 16 + g;
                    af[mt][0] = as[r0 * 36 + k0 + tg];
                    af[mt][1] = as[(r0 + 8) * 36 + k0 + tg];
                    af[mt][2] = as[r0 * 36 + k0 + 4 + tg];
                    af[mt][3] = as[(r0 + 8) * 36 + k0 + 4 + tg];
                }
#pragma unroll
                for (int nt = 0; nt < 4; ++nt) {
                    const int c0 = wn + nt * 8 + g;
                    const uint32_t b0 = ws[c0 * 36 + k0 + tg];
                    const uint32_t b1 = ws[c0 * 36 + k0 + 4 + tg];
#pragma unroll
                    for (int mt = 0; mt < 4; ++mt)
                        MMA_TF32(acc[mt][nt], af[mt][0], af[mt][1], af[mt][2],
                                 af[mt][3], b0, b1);
                }
            }
        }
        if (it + 1 < NIT) {
            uint32_t* as = AsB + (s ^ 1) * (128 * 36);
            uint32_t* ws = WsB + (s ^ 1) * (128 * 36);
#pragma unroll
            for (int i = 0; i < 4; ++i) {
                const int idx = t + 256 * i;
                const int r = idx >> 3, fq = idx & 7;
                uint4 pa, pb;
                pa.x = cvt_tf32(ra[i].x); pa.y = cvt_tf32(ra[i].y);
                pa.z = cvt_tf32(ra[i].z); pa.w = cvt_tf32(ra[i].w);
                pb.x = cvt_tf32(rw[i].x); pb.y = cvt_tf32(rw[i].y);
                pb.z = cvt_tf32(rw[i].z); pb.w = cvt_tf32(rw[i].w);
                *(uint4*)&as[r * 36 + fq * 4] = pa;
                *(uint4*)&ws[r * 36 + fq * 4] = pb;
            }
        }
        __syncthreads();
    }

#pragma unroll
    for (int mt = 0; mt < 4; ++mt) {
        const int row0 = by * 128 + wm + mt * 16 + g;
#pragma unroll
        for (int nt = 0; nt < 4; ++nt) {
            const int col = bx * 128 + wn + nt * 8 + 2 * tg;
            const float2 b01 = *(const float2*)(bias + col);
            float2 v0, v1;
            v0.x = acc[mt][nt][0] + b01.x;
            v0.y = acc[mt][nt][1] + b01.y;
            v1.x = acc[mt][nt][2] + b01.x;
            v1.y = acc[mt][nt][3] + b01.y;
            *(float2*)(C + (size_t)row0 * N + col) = v0;
            *(float2*)(C + (size_t)(row0 + 8) * N + col) = v1;
        }
    }
}

// ---------------------------------------------------------------------------
// Flash-style attention on mma.sync tf32.
// CTA = (qtile 128, head, batch), 256 threads = 8 warps; warp owns 16 q rows.
// Per k-tile (64 keys): S = Q K^T (mma), e = exp(S/8 + covbias),
// P staged via smem (tf32), E stored to g_E (bf16), O += P V (mma).
// Unnormalized single-pass softmax (scores are small, no max shift needed).
// ---------------------------------------------------------------------------
#define ATTN2_SMEM_FLOATS (128 * 68 + 64 * 68 + 64 * 68 + 128 * 68 + 64 + 128)
#define ATTN2_DSMEM (ATTN2_SMEM_FLOATS * 4)

__global__ __launch_bounds__(256) void attn_mma_kernel(
    const float* __restrict__ coverage, const float* __restrict__ Wcov)
{
    extern __shared__ float sm[];
    float* Qs = sm;                   // [q=128][d stride 68] tf32 bits
    float* Ks = Qs + 128 * 68;        // [key=64][d stride 68] tf32 bits
    float* Vt = Ks + 64 * 68;         // [dv=64][key stride 68] tf32 bits
    float* Ps = Vt + 64 * 68;         // [q=128][key stride 68] tf32 bits
    float* cb = Ps + 128 * 68;        // [64]
    float* ls = cb + 64;              // [128]

    const int qt = blockIdx.x, h = blockIdx.y, b = blockIdx.z;
    const int tid = threadIdx.x;
    const int lane = tid & 31, w = tid >> 5;
    const int g = lane >> 2, tg = lane & 3;
    const int wq = w * 16;
    const float wch = __ldg(&Wcov[h]);

    // Q tile -> smem (tf32)
    {
        const float* Qg = g_Q + ((size_t)(b * TQ + qt * 128)) * D_MODEL + h * HD;
        for (int i = tid; i < 128 * 16; i += 256) {
            int q = i >> 4, d4 = (i & 15) << 2;
            float4 v = *(const float4*)(Qg + (size_t)q * D_MODEL + d4);
            float4 p;
            p.x = tf32f(v.x); p.y = tf32f(v.y); p.z = tf32f(v.z); p.w = tf32f(v.w);
            *(float4*)(Qs + q * 68 + d4) = p;
        }
    }
    if (tid < 128) ls[tid] = 0.f;

    float accO[8][4];
#pragma unroll
    for (int nt = 0; nt < 8; ++nt)
#pragma unroll
        for (int r = 0; r < 4; ++r) accO[nt][r] = 0.f;
    float lp0 = 0.f, lp1 = 0.f;

    for (int kt = 0; kt < 16; ++kt) {
        __syncthreads();
        const float* Kg = g_K + ((size_t)(b * TK + kt * 64)) * D_MODEL + h * HD;
        const float* Vg = g_V + ((size_t)(b * TK + kt * 64)) * D_MODEL + h * HD;
        for (int i = tid; i < 64 * 16; i += 256) {
            int k = i >> 4, d4 = (i & 15) << 2;
            float4 kv = *(const float4*)(Kg + (size_t)k * D_MODEL + d4);
            float4 pk;
            pk.x = tf32f(kv.x); pk.y = tf32f(kv.y);
            pk.z = tf32f(kv.z); pk.w = tf32f(kv.w);
            *(float4*)(Ks + k * 68 + d4) = pk;
            float4 vv = *(const float4*)(Vg + (size_t)k * D_MODEL + d4);
            Vt[(d4 + 0) * 68 + k] = tf32f(vv.x);
            Vt[(d4 + 1) * 68 + k] = tf32f(vv.y);
            Vt[(d4 + 2) * 68 + k] = tf32f(vv.z);
            Vt[(d4 + 3) * 68 + k] = tf32f(vv.w);
        }
        if (tid < 64) cb[tid] = __ldg(&coverage[b * TK + kt * 64 + tid]) * wch;
        __syncthreads();

        // S = Q K^T : warp rows wq..wq+15, 64 key cols
        float s[8][4];
#pragma unroll
        for (int nt = 0; nt < 8; ++nt)
#pragma unroll
            for (int r = 0; r < 4; ++r) s[nt][r] = 0.f;
#pragma unroll
        for (int kk = 0; kk < 8; ++kk) {
            const int k0 = kk * 8;
            const uint32_t a0 = __float_as_uint(Qs[(wq + g) * 68 + k0 + tg]);
            const uint32_t a1 = __float_as_uint(Qs[(wq + g + 8) * 68 + k0 + tg]);
            const uint32_t a2 = __float_as_uint(Qs[(wq + g) * 68 + k0 + 4 + tg]);
            const uint32_t a3 = __float_as_uint(Qs[(wq + g + 8) * 68 + k0 + 4 + tg]);
#pragma unroll
            for (int nt = 0; nt < 8; ++nt) {
                const uint32_t b0 = __float_as_uint(Ks[(nt * 8 + g) * 68 + k0 + tg]);
                const uint32_t b1 = __float_as_uint(Ks[(nt * 8 + g) * 68 + k0 + 4 + tg]);
                MMA_TF32(s[nt], a0, a1, a2, a3, b0, b1);
            }
        }

        // exp + coverage bias -> Ps (tf32), accumulate row sums
#pragma unroll
        for (int nt = 0; nt < 8; ++nt) {
            const int c = nt * 8 + 2 * tg;
            const float cb0 = cb[c], cb1 = cb[c + 1];
            const float e0 = __expf(fmaf(s[nt][0], 0.125f, cb0));
            const float e1 = __expf(fmaf(s[nt][1], 0.125f, cb1));
            const float e2 = __expf(fmaf(s[nt][2], 0.125f, cb0));
            const float e3 = __expf(fmaf(s[nt][3], 0.125f, cb1));
            lp0 += e0 + e1;
            lp1 += e2 + e3;
            float2 p0, p1;
            p0.x = tf32f(e0); p0.y = tf32f(e1);
            p1.x = tf32f(e2); p1.y = tf32f(e3);
            *(float2*)(Ps + (wq + g) * 68 + c) = p0;
            *(float2*)(Ps + (wq + g + 8) * 68 + c) = p1;
        }
        __syncthreads();

        // E -> global (bf16), coalesced from Ps
        {
            __nv_bfloat16* Eg = g_E +
                (((size_t)(b * NHEAD + h) * TQ + qt * 128)) * TK + kt * 64;
            for (int i = tid; i < 2048; i += 256) {
                int row = i >> 4, c4 = (i & 15) << 2;
                float4 v = *(const float4*)(Ps + row * 68 + c4);
                __nv_bfloat162 lo = __floats2bfloat162_rn(v.x, v.y);
                __nv_bfloat162 hi = __floats2bfloat162_rn(v.z, v.w);
                uint2 pk;
                pk.x = *reinterpret_cast<uint32_t*>(&lo);
                pk.y = *reinterpret_cast<uint32_t*>(&hi);
                *reinterpret_cast<uint2*>(Eg + (size_t)row * TK + c4) = pk;
            }
        }

        // O += P V : A = Ps (q x key), B = Vt (dv x key)
#pragma unroll
        for (int kk = 0; kk < 8; ++kk) {
            const int k0 = kk * 8;
            const uint32_t a0 = __float_as_uint(Ps[(wq + g) * 68 + k0 + tg]);
            const uint32_t a1 = __float_as_uint(Ps[(wq + g + 8) * 68 + k0 + tg]);
            const uint32_t a2 = __float_as_uint(Ps[(wq + g) * 68 + k0 + 4 + tg]);
            const uint32_t a3 = __float_as_uint(Ps[(wq + g + 8) * 68 + k0 + 4 + tg]);
#pragma unroll
            for (int nt = 0; nt < 8; ++nt) {
                const uint32_t b0 = __float_as_uint(Vt[(nt * 8 + g) * 68 + k0 + tg]);
                const uint32_t b1 = __float_as_uint(Vt[(nt * 8 + g) * 68 + k0 + 4 + tg]);
                MMA_TF32(accO[nt], a0, a1, a2, a3, b0, b1);
            }
        }
    }

    // row-sum reduction across the quad lanes (tg), then smem atomics
    lp0 += __shfl_xor_sync(0xffffffffu, lp0, 1);
    lp0 += __shfl_xor_sync(0xffffffffu, lp0, 2);
    lp1 += __shfl_xor_sync(0xffffffffu, lp1, 1);
    lp1 += __shfl_xor_sync(0xffffffffu, lp1, 2);
    if (tg == 0) {
        atomicAdd(&ls[wq + g], lp0);
        atomicAdd(&ls[wq + g + 8], lp1);
    }
    __syncthreads();

    const float inv0 = 1.f / ls[wq + g];
    const float inv1 = 1.f / ls[wq + g + 8];
    float* Og = g_O + ((size_t)(b * TQ + qt * 128)) * D_MODEL + h * HD;
#pragma unroll
    for (int nt = 0; nt < 8; ++nt) {
        const int c = nt * 8 + 2 * tg;
        float2 o0, o1;
        o0.x = accO[nt][0] * inv0; o0.y = accO[nt][1] * inv0;
        o1.x = accO[nt][2] * inv1; o1.y = accO[nt][3] * inv1;
        *(float2*)(Og + (size_t)(wq + g) * D_MODEL + c) = o0;
        *(float2*)(Og + (size_t)(wq + g + 8) * D_MODEL + c) = o1;
    }
    if (tid < 128)
        g_L[((size_t)b * NHEAD + h) * TQ + qt * 128 + tid] = ls[tid];
}

// ---------------------------------------------------------------------------
// Coverage reduction: covout[b,k] += sum_{h,q} E[b,h,q,k] / (16 * l[b,h,q])
// grid (qchunk=8, NHEAD, BATCH), 256 threads; thread covers 4 k's.
// ---------------------------------------------------------------------------
__global__ __launch_bounds__(256) void cov_reduce_kernel(float* __restrict__ covout)
{
    __shared__ float il[128];
    const int qc = blockIdx.x, h = blockIdx.y, b = blockIdx.z;
    const int tid = threadIdx.x;
    if (tid < 128)
        il[tid] = 1.f / (16.f * g_L[((size_t)b * NHEAD + h) * TQ + qc * 128 + tid]);
    __syncthreads();

    const __nv_bfloat16* E = g_E +
        ((size_t)(b * NHEAD + h) * TQ + qc * 128) * TK;
    const int k0 = tid * 4;
    float a0 = 0.f, a1 = 0.f, a2 = 0.f, a3 = 0.f;
#pragma unroll 4
    for (int q = 0; q < 128; ++q) {
        uint2 p = *reinterpret_cast<const uint2*>(E + (size_t)q * TK + k0);
        const float wq = il[q];
        __nv_bfloat162 lo = *reinterpret_cast<__nv_bfloat162*>(&p.x);
        __nv_bfloat162 hi = *reinterpret_cast<__nv_bfloat162*>(&p.y);
        a0 = fmaf(__bfloat162float(lo.x), wq, a0);
        a1 = fmaf(__bfloat162float(lo.y), wq, a1);
        a2 = fmaf(__bfloat162float(hi.x), wq, a2);
        a3 = fmaf(__bfloat162float(hi.y), wq, a3);
    }
    atomicAdd(&covout[b * TK + k0 + 0], a0);
    atomicAdd(&covout[b * TK + k0 + 1], a1);
    atomicAdd(&covout[b * TK + k0 + 2], a2);
    atomicAdd(&covout[b * TK + k0 + 3], a3);
}

__global__ void cov_init_kernel(const float* __restrict__ coverage,
                                float* __restrict__ covout)
{
    int i = blockIdx.x * blockDim.x + threadIdx.x;
    if (i < BATCH * TK) covout[i] = coverage[i];
}

// ---------------------------------------------------------------------------
extern "C" void kernel_launch(void* const* d_in, const int* in_sizes, int n_in,
                              void* d_out, int out_size)
{
    const float* query    = (const float*)d_in[0];
    const float* memory   = (const float*)d_in[1];
    const float* coverage = (const float*)d_in[2];
    const float* Wq = (const float*)d_in[3];
    const float* bq = (const float*)d_in[4];
    const float* Wk = (const float*)d_in[5];
    const float* bk = (const float*)d_in[6];
    const float* Wv = (const float*)d_in[7];
    const float* bv = (const float*)d_in[8];
    const float* Wo = (const float*)d_in[9];
    const float* bo = (const float*)d_in[10];
    const float* Wcov = (const float*)d_in[11];

    float* out = (float*)d_out;
    float* covout = out + (size_t)BATCH * TQ * D_MODEL;

    float *Qp, *Kp, *Vp, *Op;
    cudaGetSymbolAddress((void**)&Qp, g_Q);
    cudaGetSymbolAddress((void**)&Kp, g_K);
    cudaGetSymbolAddress((void**)&Vp, g_V);
    cudaGetSymbolAddress((void**)&Op, g_O);

    const int M = BATCH * TQ;   // 8192
    const dim3 ggrid(D_MODEL / 128, M / 128);

    cudaFuncSetAttribute(gemm_mma_kernel, cudaFuncAttributeMaxDynamicSharedMemorySize,
                         GEMM_DSMEM);
    cudaFuncSetAttribute(attn_mma_kernel, cudaFuncAttributeMaxDynamicSharedMemorySize,
                         ATTN2_DSMEM);

    gemm_mma_kernel<<<ggrid, 256, GEMM_DSMEM>>>(query,  Wq, bq, Qp, M, D_MODEL, D_MODEL);
    gemm_mma_kernel<<<ggrid, 256, GEMM_DSMEM>>>(memory, Wk, bk, Kp, M, D_MODEL, D_MODEL);
    gemm_mma_kernel<<<ggrid, 256, GEMM_DSMEM>>>(memory, Wv, bv, Vp, M, D_MODEL, D_MODEL);

    attn_mma_kernel<<<dim3(TQ / 128, NHEAD, BATCH), 256, ATTN2_DSMEM>>>(coverage, Wcov);

    gemm_mma_kernel<<<ggrid, 256, GEMM_DSMEM>>>(Op, Wo, bo, out, M, D_MODEL, D_MODEL);

    cov_init_kernel<<<(BATCH * TK + 255) / 256, 256>>>(coverage, covout);
    cov_reduce_kernel<<<dim3(TQ / 128, NHEAD, BATCH), 256>>>(covout);
}